// round 1
// baseline (speedup 1.0000x reference)
#include <cuda_runtime.h>

#define BB 32
#define NN 128
#define HH 100
#define ROWS (BB*NN)   // 4096

// Scratch (static device allocations — allowed)
__device__ float g_hidden[ROWS*HH];
__device__ float g_hv[ROWS*HH];
__device__ float g_hw[ROWS*HH];
__device__ float g_msg[ROWS*HH];
__device__ float g_gterm[ROWS*HH];
__device__ int   g_nodemask[ROWS];

// ---------------------------------------------------------------------------
// init: hidden = nodes; node_mask[row] = (sum_w sum_e edges[row,w,e]) != 0
// grid = 4096 blocks (one per (b,v) row), 128 threads
// ---------------------------------------------------------------------------
__global__ void k_init(const float* __restrict__ nodes,
                       const float* __restrict__ edges) {
    int row = blockIdx.x;
    int tid = threadIdx.x;
    if (tid < HH) g_hidden[row*HH + tid] = nodes[row*HH + tid];

    const float4* e4 = (const float4*)edges + (size_t)row * NN;
    float4 e = e4[tid];
    float s = (e.x + e.y) + (e.z + e.w);
    __shared__ float red[128];
    red[tid] = s;
    __syncthreads();
    for (int off = 64; off > 0; off >>= 1) {
        if (tid < off) red[tid] += red[tid + off];
        __syncthreads();
    }
    if (tid == 0) g_nodemask[row] = (red[0] != 0.0f) ? 1 : 0;
}

// ---------------------------------------------------------------------------
// proj: hv = hidden @ Wv, hw = hidden @ Ww. 8 rows per block to amortize
// weight LDGs (1 LDG feeds 8 FMAs). grid = 512, 128 threads.
// ---------------------------------------------------------------------------
__global__ void k_proj(const float* __restrict__ Wv,
                       const float* __restrict__ Ww) {
    int base = blockIdx.x * 8;
    int tid = threadIdx.x;
    __shared__ float s_rows[8*HH];
    for (int i = tid; i < 8*HH; i += 128) s_rows[i] = g_hidden[base*HH + i];
    __syncthreads();
    if (tid < HH) {
        int h = tid;
        float av[8], aw[8];
        #pragma unroll
        for (int r = 0; r < 8; r++) { av[r] = 0.f; aw[r] = 0.f; }
        for (int k = 0; k < HH; k++) {
            float wv = Wv[k*HH + h];
            float ww = Ww[k*HH + h];
            #pragma unroll
            for (int r = 0; r < 8; r++) {
                float x = s_rows[r*HH + k];
                av[r] = fmaf(x, wv, av[r]);
                aw[r] = fmaf(x, ww, aw[r]);
            }
        }
        #pragma unroll
        for (int r = 0; r < 8; r++) {
            g_hv[(base + r)*HH + h] = av[r];
            g_hw[(base + r)*HH + h] = aw[r];
        }
    }
}

// ---------------------------------------------------------------------------
// msg: messages[b,v,h] = sum_w [adj(b,v,w)!=0] * relu(hv[b,v,h] + hw[b,w,h]
//                                + sum_e edges[b,v,w,e]*We[e,h])
// One block per (b, group of 4 v). 512 threads = (vloc, h).
// Dynamic shared: hw tile for whole batch b (51200B) + edges for 4 rows
// (8192B float4) + adjacency sums (2048B) = 61440B.
// ---------------------------------------------------------------------------
__global__ void k_msg(const float* __restrict__ edges,
                      const float* __restrict__ We) {
    extern __shared__ float smem[];
    float*  s_hw  = smem;                        // 12800 floats
    float4* s_e   = (float4*)(smem + 12800);     // 512 float4
    float*  s_adj = smem + 12800 + 2048;         // 512 floats

    int bx  = blockIdx.x;         // 0..1023
    int b   = bx >> 5;
    int v0  = (bx & 31) * 4;
    int tid = threadIdx.x;        // 512

    for (int i = tid; i < NN*HH; i += 512)
        s_hw[i] = g_hw[(b*NN)*HH + i];
    {
        int vloc = tid >> 7, w = tid & 127;
        const float4* e4 = (const float4*)edges;
        float4 e = e4[(size_t)((b*NN + v0 + vloc) * NN) + w];
        s_e[tid]   = e;
        s_adj[tid] = (e.x + e.y) + (e.z + e.w);
    }
    __syncthreads();

    int vloc = tid >> 7;
    int h    = tid & 127;
    if (h < HH) {
        float we0 = We[h], we1 = We[HH + h], we2 = We[2*HH + h], we3 = We[3*HH + h];
        float hvh = g_hv[(b*NN + v0 + vloc)*HH + h];
        const float4* ev = s_e  + (vloc << 7);
        const float*  av = s_adj + (vloc << 7);
        float acc = 0.f;
        #pragma unroll 4
        for (int w = 0; w < NN; w++) {
            float4 e   = ev[w];
            float  pre = hvh + s_hw[w*HH + h];
            pre = fmaf(e.x, we0, pre);
            pre = fmaf(e.y, we1, pre);
            pre = fmaf(e.z, we2, pre);
            pre = fmaf(e.w, we3, pre);
            acc += (av[w] != 0.f) ? fmaxf(pre, 0.f) : 0.f;
        }
        g_msg[(b*NN + v0 + vloc)*HH + h] = acc;
    }
}

// ---------------------------------------------------------------------------
// update: hidden = node_mask ? tanh([hidden, msg] @ Wu) : hidden
// 8 rows per block. In-place safe: each block touches only its own rows.
// ---------------------------------------------------------------------------
__global__ void k_update(const float* __restrict__ Wu) {
    int base = blockIdx.x * 8;
    int tid  = threadIdx.x;
    __shared__ float s_h[8*HH];
    __shared__ float s_m[8*HH];
    for (int i = tid; i < 8*HH; i += 128) {
        s_h[i] = g_hidden[base*HH + i];
        s_m[i] = g_msg[base*HH + i];
    }
    __syncthreads();
    if (tid < HH) {
        int h = tid;
        float acc[8];
        #pragma unroll
        for (int r = 0; r < 8; r++) acc[r] = 0.f;
        for (int k = 0; k < HH; k++) {
            float w1 = Wu[k*HH + h];
            #pragma unroll
            for (int r = 0; r < 8; r++) acc[r] = fmaf(s_h[r*HH + k], w1, acc[r]);
        }
        for (int k = 0; k < HH; k++) {
            float w2 = Wu[(HH + k)*HH + h];
            #pragma unroll
            for (int r = 0; r < 8; r++) acc[r] = fmaf(s_m[r*HH + k], w2, acc[r]);
        }
        #pragma unroll
        for (int r = 0; r < 8; r++) {
            float nh = g_nodemask[base + r] ? tanhf(acc[r]) : s_h[r*HH + h];
            g_hidden[(base + r)*HH + h] = nh;
        }
    }
}

// ---------------------------------------------------------------------------
// readout terms: gterm = node_mask ? relu([hidden, nodes] @ Wr) : 0
// ---------------------------------------------------------------------------
__global__ void k_readout(const float* __restrict__ nodes,
                          const float* __restrict__ Wr) {
    int base = blockIdx.x * 8;
    int tid  = threadIdx.x;
    __shared__ float s_h[8*HH];
    __shared__ float s_n[8*HH];
    for (int i = tid; i < 8*HH; i += 128) {
        s_h[i] = g_hidden[base*HH + i];
        s_n[i] = nodes[base*HH + i];
    }
    __syncthreads();
    if (tid < HH) {
        int h = tid;
        float acc[8];
        #pragma unroll
        for (int r = 0; r < 8; r++) acc[r] = 0.f;
        for (int k = 0; k < HH; k++) {
            float w1 = Wr[k*HH + h];
            #pragma unroll
            for (int r = 0; r < 8; r++) acc[r] = fmaf(s_h[r*HH + k], w1, acc[r]);
        }
        for (int k = 0; k < HH; k++) {
            float w2 = Wr[(HH + k)*HH + h];
            #pragma unroll
            for (int r = 0; r < 8; r++) acc[r] = fmaf(s_n[r*HH + k], w2, acc[r]);
        }
        #pragma unroll
        for (int r = 0; r < 8; r++) {
            float g = fmaxf(acc[r], 0.f);
            g_gterm[(base + r)*HH + h] = g_nodemask[base + r] ? g : 0.f;
        }
    }
}

// ---------------------------------------------------------------------------
// reduce: out[b,h] = sum_v gterm[b,v,h]  (deterministic, no atomics)
// ---------------------------------------------------------------------------
__global__ void k_reduce(float* __restrict__ out) {
    int b = blockIdx.x;
    int h = threadIdx.x;
    if (h < HH) {
        float acc = 0.f;
        #pragma unroll 4
        for (int v = 0; v < NN; v++)
            acc += g_gterm[(b*NN + v)*HH + h];
        out[b*HH + h] = acc;
    }
}

extern "C" void kernel_launch(void* const* d_in, const int* in_sizes, int n_in,
                              void* d_out, int out_size) {
    const float* nodes = (const float*)d_in[0];
    const float* edges = (const float*)d_in[1];
    const float* Wv    = (const float*)d_in[2];
    const float* Ww    = (const float*)d_in[3];
    const float* We    = (const float*)d_in[4];
    const float* Wu    = (const float*)d_in[5];
    const float* Wr    = (const float*)d_in[6];
    float* out = (float*)d_out;

    // opt-in to >48KB dynamic shared for k_msg (not a stream op; capture-safe)
    cudaFuncSetAttribute(k_msg, cudaFuncAttributeMaxDynamicSharedMemorySize, 61440);

    k_init<<<ROWS, 128>>>(nodes, edges);
    for (int p = 0; p < 3; p++) {
        k_proj<<<ROWS/8, 128>>>(Wv, Ww);
        k_msg<<<1024, 512, 61440>>>(edges, We);
        k_update<<<ROWS/8, 128>>>(Wu);
    }
    k_readout<<<ROWS/8, 128>>>(nodes, Wr);
    k_reduce<<<BB, 128>>>(out);
}

// round 2
// speedup vs baseline: 1.1169x; 1.1169x over previous
#include <cuda_runtime.h>

#define BB 32
#define NN 128
#define HH 100
#define ROWS (BB*NN)   // 4096

// Scratch (static device allocations — allowed)
__device__ float g_hidden[ROWS*HH];
__device__ float g_hv[ROWS*HH];
__device__ float g_hw[ROWS*HH];
__device__ float g_msg[ROWS*HH];
__device__ float g_gterm[ROWS*HH];
__device__ int   g_nodemask[ROWS];

// ---------------------------------------------------------------------------
// init: hidden = nodes; node_mask[row] = (sum_w sum_e edges[row,w,e]) != 0
// ---------------------------------------------------------------------------
__global__ void k_init(const float* __restrict__ nodes,
                       const float* __restrict__ edges) {
    int row = blockIdx.x;
    int tid = threadIdx.x;
    if (tid < HH) g_hidden[row*HH + tid] = nodes[row*HH + tid];

    const float4* e4 = (const float4*)edges + (size_t)row * NN;
    float4 e = e4[tid];
    float s = (e.x + e.y) + (e.z + e.w);
    __shared__ float red[128];
    red[tid] = s;
    __syncthreads();
    for (int off = 64; off > 0; off >>= 1) {
        if (tid < off) red[tid] += red[tid + off];
        __syncthreads();
    }
    if (tid == 0) g_nodemask[row] = (red[0] != 0.0f) ? 1 : 0;
}

// ---------------------------------------------------------------------------
// proj: hv = hidden @ Wv, hw = hidden @ Ww.
// 4 rows/block, grid=1024. Rows staged TRANSPOSED in shared: sT[k] holds the
// 4 rows' element k as a float4 -> inner loop = 1 broadcast LDS.128 + 2 LDG
// + 8 FMA.
// ---------------------------------------------------------------------------
__global__ void k_proj(const float* __restrict__ Wv,
                       const float* __restrict__ Ww) {
    int base = blockIdx.x * 4;
    int tid  = threadIdx.x;
    __shared__ float4 sT[HH];
    float* sTf = (float*)sT;
    for (int i = tid; i < 4*HH; i += 128) {
        int r = i / HH, k = i - r*HH;
        sTf[k*4 + r] = g_hidden[(base + r)*HH + k];
    }
    __syncthreads();
    if (tid < HH) {
        int h = tid;
        float av0=0.f, av1=0.f, av2=0.f, av3=0.f;
        float aw0=0.f, aw1=0.f, aw2=0.f, aw3=0.f;
        #pragma unroll 4
        for (int k = 0; k < HH; k++) {
            float4 x = sT[k];
            float wv = Wv[k*HH + h];
            float ww = Ww[k*HH + h];
            av0 = fmaf(x.x, wv, av0); av1 = fmaf(x.y, wv, av1);
            av2 = fmaf(x.z, wv, av2); av3 = fmaf(x.w, wv, av3);
            aw0 = fmaf(x.x, ww, aw0); aw1 = fmaf(x.y, ww, aw1);
            aw2 = fmaf(x.z, ww, aw2); aw3 = fmaf(x.w, ww, aw3);
        }
        g_hv[(base+0)*HH + h] = av0; g_hv[(base+1)*HH + h] = av1;
        g_hv[(base+2)*HH + h] = av2; g_hv[(base+3)*HH + h] = av3;
        g_hw[(base+0)*HH + h] = aw0; g_hw[(base+1)*HH + h] = aw1;
        g_hw[(base+2)*HH + h] = aw2; g_hw[(base+3)*HH + h] = aw3;
    }
}

// ---------------------------------------------------------------------------
// msg: messages[b,v,h] = sum_w [adj!=0] * relu(hv[v,h] + hw[w,h] + e.We)
// (unchanged from R1 — not the bottleneck)
// ---------------------------------------------------------------------------
__global__ void k_msg(const float* __restrict__ edges,
                      const float* __restrict__ We) {
    extern __shared__ float smem[];
    float*  s_hw  = smem;                        // 12800 floats
    float4* s_e   = (float4*)(smem + 12800);     // 512 float4
    float*  s_adj = smem + 12800 + 2048;         // 512 floats

    int bx  = blockIdx.x;
    int b   = bx >> 5;
    int v0  = (bx & 31) * 4;
    int tid = threadIdx.x;

    for (int i = tid; i < NN*HH; i += 512)
        s_hw[i] = g_hw[(b*NN)*HH + i];
    {
        int vloc = tid >> 7, w = tid & 127;
        const float4* e4 = (const float4*)edges;
        float4 e = e4[(size_t)((b*NN + v0 + vloc) * NN) + w];
        s_e[tid]   = e;
        s_adj[tid] = (e.x + e.y) + (e.z + e.w);
    }
    __syncthreads();

    int vloc = tid >> 7;
    int h    = tid & 127;
    if (h < HH) {
        float we0 = We[h], we1 = We[HH + h], we2 = We[2*HH + h], we3 = We[3*HH + h];
        float hvh = g_hv[(b*NN + v0 + vloc)*HH + h];
        const float4* ev = s_e  + (vloc << 7);
        const float*  av = s_adj + (vloc << 7);
        float acc = 0.f;
        #pragma unroll 4
        for (int w = 0; w < NN; w++) {
            float4 e   = ev[w];
            float  pre = hvh + s_hw[w*HH + h];
            pre = fmaf(e.x, we0, pre);
            pre = fmaf(e.y, we1, pre);
            pre = fmaf(e.z, we2, pre);
            pre = fmaf(e.w, we3, pre);
            acc += (av[w] != 0.f) ? fmaxf(pre, 0.f) : 0.f;
        }
        g_msg[(b*NN + v0 + vloc)*HH + h] = acc;
    }
}

// ---------------------------------------------------------------------------
// update: hidden = node_mask ? tanh([hidden, msg] @ Wu) : hidden
// 4 rows/block, transposed staging of the 200-deep concat.
// ---------------------------------------------------------------------------
__global__ void k_update(const float* __restrict__ Wu) {
    int base = blockIdx.x * 4;
    int tid  = threadIdx.x;
    __shared__ float4 sT[2*HH];    // k 0..99 = hidden, 100..199 = msg
    float* sTf = (float*)sT;
    for (int i = tid; i < 4*HH; i += 128) {
        int r = i / HH, k = i - r*HH;
        sTf[k*4 + r]          = g_hidden[(base + r)*HH + k];
        sTf[(HH + k)*4 + r]   = g_msg   [(base + r)*HH + k];
    }
    __syncthreads();
    if (tid < HH) {
        int h = tid;
        float a0=0.f, a1=0.f, a2=0.f, a3=0.f;
        #pragma unroll 4
        for (int k = 0; k < 2*HH; k++) {
            float4 x = sT[k];
            float w = Wu[k*HH + h];
            a0 = fmaf(x.x, w, a0); a1 = fmaf(x.y, w, a1);
            a2 = fmaf(x.z, w, a2); a3 = fmaf(x.w, w, a3);
        }
        float acc[4] = {a0, a1, a2, a3};
        #pragma unroll
        for (int r = 0; r < 4; r++) {
            float oldv = sTf[h*4 + r];
            g_hidden[(base + r)*HH + h] =
                g_nodemask[base + r] ? tanhf(acc[r]) : oldv;
        }
    }
}

// ---------------------------------------------------------------------------
// readout terms: gterm = node_mask ? relu([hidden, nodes] @ Wr) : 0
// ---------------------------------------------------------------------------
__global__ void k_readout(const float* __restrict__ nodes,
                          const float* __restrict__ Wr) {
    int base = blockIdx.x * 4;
    int tid  = threadIdx.x;
    __shared__ float4 sT[2*HH];
    float* sTf = (float*)sT;
    for (int i = tid; i < 4*HH; i += 128) {
        int r = i / HH, k = i - r*HH;
        sTf[k*4 + r]        = g_hidden[(base + r)*HH + k];
        sTf[(HH + k)*4 + r] = nodes   [(base + r)*HH + k];
    }
    __syncthreads();
    if (tid < HH) {
        int h = tid;
        float a0=0.f, a1=0.f, a2=0.f, a3=0.f;
        #pragma unroll 4
        for (int k = 0; k < 2*HH; k++) {
            float4 x = sT[k];
            float w = Wr[k*HH + h];
            a0 = fmaf(x.x, w, a0); a1 = fmaf(x.y, w, a1);
            a2 = fmaf(x.z, w, a2); a3 = fmaf(x.w, w, a3);
        }
        float acc[4] = {a0, a1, a2, a3};
        #pragma unroll
        for (int r = 0; r < 4; r++) {
            float g = fmaxf(acc[r], 0.f);
            g_gterm[(base + r)*HH + h] = g_nodemask[base + r] ? g : 0.f;
        }
    }
}

// ---------------------------------------------------------------------------
// reduce: out[b,h] = sum_v gterm[b,v,h]  (deterministic, no atomics)
// 512 threads: 4-way v-split + shared combine.
// ---------------------------------------------------------------------------
__global__ void k_reduce(float* __restrict__ out) {
    int b   = blockIdx.x;
    int tid = threadIdx.x;           // 512
    int q   = tid >> 7;
    int h   = tid & 127;
    __shared__ float red[4][128];
    float acc = 0.f;
    if (h < HH) {
        int v0 = q * 32;
        #pragma unroll 4
        for (int v = v0; v < v0 + 32; v++)
            acc += g_gterm[(b*NN + v)*HH + h];
    }
    red[q][h] = acc;
    __syncthreads();
    if (q == 0 && h < HH)
        out[b*HH + h] = (red[0][h] + red[1][h]) + (red[2][h] + red[3][h]);
}

extern "C" void kernel_launch(void* const* d_in, const int* in_sizes, int n_in,
                              void* d_out, int out_size) {
    const float* nodes = (const float*)d_in[0];
    const float* edges = (const float*)d_in[1];
    const float* Wv    = (const float*)d_in[2];
    const float* Ww    = (const float*)d_in[3];
    const float* We    = (const float*)d_in[4];
    const float* Wu    = (const float*)d_in[5];
    const float* Wr    = (const float*)d_in[6];
    float* out = (float*)d_out;

    cudaFuncSetAttribute(k_msg, cudaFuncAttributeMaxDynamicSharedMemorySize, 61440);

    k_init<<<ROWS, 128>>>(nodes, edges);
    for (int p = 0; p < 3; p++) {
        k_proj<<<ROWS/4, 128>>>(Wv, Ww);
        k_msg<<<1024, 512, 61440>>>(edges, We);
        k_update<<<ROWS/4, 128>>>(Wu);
    }
    k_readout<<<ROWS/4, 128>>>(nodes, Wr);
    k_reduce<<<BB, 512>>>(out);
}